// round 10
// baseline (speedup 1.0000x reference)
#include <cuda_runtime.h>
#include <cuda_fp16.h>
#include <math.h>
#include <stdint.h>

// Problem constants
#define NN    6144
#define DD    128
#define NCLS  20
#define NB    5

#define ITILES 48                     // 6144/128
#define NPAIRS (ITILES*(ITILES+1)/2)  // 1176 tile pairs (I<=J)
#define JSPLIT ITILES

#define TBLK  384                     // k_tail blocks (16 rows each)

// SMEM layout for k_main. Tile rows = 256B (128 fp16), 16B-chunk XOR swizzle.
#define OFF_A    0
#define OFF_B    32768
#define OFF_TI   65536
#define OFF_BI   (OFF_TI + 512)
#define OFF_TJ   (OFF_BI + 512)
#define OFF_BJ   (OFF_TJ + 512)
#define OFF_RED1 OFF_A                // aliased onto dead A tile
#define OFF_RED2 (OFF_A + 8192)
#define SMEM_TOTAL (OFF_BJ + 512)     // ~67.5KB -> 2 CTA/SM

__device__ __forceinline__ uint32_t smem_u32(const void* p) {
    uint32_t a;
    asm("{ .reg .u64 t; cvta.to.shared.u64 t, %1; cvt.u32.u64 %0, t; }" : "=r"(a) : "l"(p));
    return a;
}

#define LDSM_X4(r0, r1, r2, r3, addr) \
    asm volatile("ldmatrix.sync.aligned.m8n8.x4.shared.b16 {%0,%1,%2,%3}, [%4];" \
                 : "=r"(r0), "=r"(r1), "=r"(r2), "=r"(r3) : "r"(addr))

#define MMA_F16(c, a, b0, b1) \
    asm volatile("mma.sync.aligned.m16n8k16.row.col.f32.f16.f16.f32 " \
                 "{%0,%1,%2,%3}, {%4,%5,%6,%7}, {%8,%9}, {%0,%1,%2,%3};" \
                 : "+f"((c)[0]), "+f"((c)[1]), "+f"((c)[2]), "+f"((c)[3]) \
                 : "r"((a)[0]), "r"((a)[1]), "r"((a)[2]), "r"((a)[3]), "r"(b0), "r"(b1))

// ---------------- Scratch (device globals) ----------------
__device__ __half g_h[NN * DD];
__device__ float g_part[NN * JSPLIT * 4];   // [row][split][4] row-major
__device__ int   g_hist_t[NCLS];
__device__ int   g_hist_tb[NCLS * NB];
__device__ float g_blk[TBLK * 32];

// ---------------------------------------------------------------------------
// Kernel 1: normalize + fp16 convert.  Two rows per warp.
// ---------------------------------------------------------------------------
__global__ void k_norm(const float* __restrict__ x) {
    int row0 = blockIdx.x * 16 + (threadIdx.x >> 5) * 2;
    int lane = threadIdx.x & 31;
    float4 v0 = *(const float4*)(x + (size_t)row0 * DD + lane * 4);
    float4 v1 = *(const float4*)(x + (size_t)(row0 + 1) * DD + lane * 4);
    float s0 = v0.x * v0.x + v0.y * v0.y + v0.z * v0.z + v0.w * v0.w;
    float s1 = v1.x * v1.x + v1.y * v1.y + v1.z * v1.z + v1.w * v1.w;
    #pragma unroll
    for (int o = 16; o; o >>= 1) {
        s0 += __shfl_xor_sync(0xffffffffu, s0, o);
        s1 += __shfl_xor_sync(0xffffffffu, s1, o);
    }
    float i0 = 1.0f / fmaxf(sqrtf(s0), 1e-8f);
    float i1 = 1.0f / fmaxf(sqrtf(s1), 1e-8f);
    size_t b0 = (size_t)row0 * DD + lane * 4;
    *(__half2*)(g_h + b0)          = __floats2half2_rn(v0.x * i0, v0.y * i0);
    *(__half2*)(g_h + b0 + 2)      = __floats2half2_rn(v0.z * i0, v0.w * i0);
    *(__half2*)(g_h + b0 + DD)     = __floats2half2_rn(v1.x * i1, v1.y * i1);
    *(__half2*)(g_h + b0 + DD + 2) = __floats2half2_rn(v1.z * i1, v1.w * i1);
}

// ---------------------------------------------------------------------------
// Kernel 1b: histograms (int atomics -> order independent, deterministic).
// ---------------------------------------------------------------------------
__global__ void k_hist(const int* __restrict__ targets, const int* __restrict__ batch0) {
    __shared__ int ht[NCLS], htb[NCLS * NB];
    int tid = threadIdx.x;
    if (tid < NCLS)      ht[tid]  = 0;
    if (tid < NCLS * NB) htb[tid] = 0;
    __syncthreads();
    for (int i = tid; i < NN; i += blockDim.x) {
        int t = targets[i], b = batch0[i];
        atomicAdd(&ht[t], 1);
        atomicAdd(&htb[t * NB + b], 1);
    }
    __syncthreads();
    if (tid < NCLS)      g_hist_t[tid]  = ht[tid];
    if (tid < NCLS * NB) g_hist_tb[tid] = htb[tid];
}

// ---------------------------------------------------------------------------
// Kernel 2: one CTA per tile pair (I,J), I<=J.  fp16 HMMA + TWO-PASS epilogue
// (pass A: side-1, mi-sliced; pass B: side-2, ni-sliced) so peak live regs
// stay under 128 -> genuine occupancy 2 without spills.
// ---------------------------------------------------------------------------
__device__ __forceinline__ void fill_tile(char* smem, int off,
                                          const __half* __restrict__ src,
                                          int rowbase, int tid) {
    #pragma unroll
    for (int it = 0; it < 8; it++) {
        int lin = it * 256 + tid;
        int n   = lin >> 4;
        int c16 = lin & 15;
        uint4 v = *(const uint4*)(src + (size_t)(rowbase + n) * DD + c16 * 8);
        *(uint4*)(smem + off + n * 256 + ((c16 ^ (n & 7)) << 4)) = v;
    }
}

__global__ void __launch_bounds__(256, 2)
k_main(const float* __restrict__ d_temp,
       const int*   __restrict__ targets,
       const int*   __restrict__ batch0) {
    extern __shared__ char smem[];
    const uint32_t sb = smem_u32(smem);
    const int tid = threadIdx.x;
    const int L   = tid & 31;
    const int w   = tid >> 5;
    const int wm  = w & 1;
    const int wn  = w >> 1;

    int p = blockIdx.x, I = 0;
    while (p >= ITILES - I) { p -= ITILES - I; I++; }
    const int J = I + p;
    const int Ibase = I * 128;
    const int Jbase = J * 128;
    const bool diag = (I == J);

    int*   sm_ti = (int*)(smem + OFF_TI);
    int*   sm_bi = (int*)(smem + OFF_BI);
    int*   sm_tj = (int*)(smem + OFF_TJ);
    int*   sm_bj = (int*)(smem + OFF_BJ);
    float* red1  = (float*)(smem + OFF_RED1);
    float* red2  = (float*)(smem + OFF_RED2);

    const float t     = fminf(fmaxf(d_temp[0], 0.1f), 1.0f);
    const float inv_t = 1.0f / t;

    fill_tile(smem, OFF_A, g_h, Ibase, tid);
    fill_tile(smem, OFF_B, g_h, Jbase, tid);
    if (tid < 128) {
        sm_ti[tid] = targets[Ibase + tid];
        sm_bi[tid] = batch0[Ibase + tid];
    } else {
        int r = tid - 128;
        sm_tj[r] = targets[Jbase + r];
        sm_bj[r] = batch0[Jbase + r];
    }
    __syncthreads();

    const int la15 = L & 15;
    const int l4   = L >> 4;
    const int lb7  = (L & 7) + ((L >> 4) << 3);
    const int lb1  = (L >> 3) & 1;

    float acc[4][4][4];
    #pragma unroll
    for (int mi = 0; mi < 4; mi++)
        #pragma unroll
        for (int ni = 0; ni < 4; ni++)
            #pragma unroll
            for (int e = 0; e < 4; e++) acc[mi][ni][e] = 0.f;

    #pragma unroll
    for (int ks = 0; ks < 8; ks++) {
        uint32_t a[4][4], b[2][4];
        #pragma unroll
        for (int mi = 0; mi < 4; mi++) {
            int rowA = wm * 64 + mi * 16 + la15;
            uint32_t ad = sb + OFF_A + rowA * 256 + (((ks * 2 + l4) ^ (rowA & 7)) << 4);
            LDSM_X4(a[mi][0], a[mi][1], a[mi][2], a[mi][3], ad);
        }
        #pragma unroll
        for (int np = 0; np < 2; np++) {
            int rowB = wn * 32 + np * 16 + lb7;
            uint32_t bd = sb + OFF_B + rowB * 256 + (((ks * 2 + lb1) ^ (rowB & 7)) << 4);
            LDSM_X4(b[np][0], b[np][1], b[np][2], b[np][3], bd);
        }
        #pragma unroll
        for (int mi = 0; mi < 4; mi++)
            #pragma unroll
            for (int ni = 0; ni < 4; ni++)
                MMA_F16(acc[mi][ni], a[mi],
                        b[ni >> 1][(ni & 1) * 2], b[ni >> 1][(ni & 1) * 2 + 1]);
    }

    __syncthreads();   // LDSM reads of A done; red buffers (alias A) safe

    const int g = L >> 2, q = L & 3;

    // ---- Pass A: side-1 (rows of I), mi-sliced: only 8 partial regs live ----
    #pragma unroll
    for (int mi = 0; mi < 4; mi++) {
        float s1[2][4];
        #pragma unroll
        for (int h = 0; h < 2; h++)
            #pragma unroll
            for (int c = 0; c < 4; c++) s1[h][c] = 0.f;

        #pragma unroll
        for (int ni = 0; ni < 4; ni++) {
            #pragma unroll
            for (int e = 0; e < 4; e++) {
                int h     = e >> 1;
                int i_loc = wm * 64 + mi * 16 + h * 8 + g;
                int j_loc = wn * 32 + ni * 8 + 2 * q + (e & 1);
                float s  = acc[mi][ni][e];
                float et = __expf(s * inv_t);
                bool same_t = (sm_ti[i_loc] == sm_tj[j_loc]);
                bool self   = diag && (i_loc == j_loc);
                if (same_t) {
                    if (!self) {
                        float eb = __expf(s * 2.0f);   // 1/TEMP_BATCH
                        s1[h][0] += et;
                        if (sm_bi[i_loc] == sm_bj[j_loc]) s1[h][2] += eb;
                        else                              s1[h][3] += eb;
                    }
                } else {
                    s1[h][1] += et;
                }
            }
        }
        #pragma unroll
        for (int h = 0; h < 2; h++) {
            float a = s1[h][0], b = s1[h][1], c = s1[h][2], d = s1[h][3];
            #pragma unroll
            for (int o = 1; o <= 2; o <<= 1) {
                a += __shfl_xor_sync(0xffffffffu, a, o);
                b += __shfl_xor_sync(0xffffffffu, b, o);
                c += __shfl_xor_sync(0xffffffffu, c, o);
                d += __shfl_xor_sync(0xffffffffu, d, o);
            }
            if (q == 0) {
                int row_loc = wm * 64 + mi * 16 + h * 8 + g;
                *(float4*)&red1[(wn * 128 + row_loc) * 4] = make_float4(a, b, c, d);
            }
        }
    }

    // ---- Pass B: side-2 (rows of J), ni-sliced: only 8 partial regs live ----
    if (!diag) {
        #pragma unroll
        for (int ni = 0; ni < 4; ni++) {
            float s2[2][4];
            #pragma unroll
            for (int h = 0; h < 2; h++)
                #pragma unroll
                for (int c = 0; c < 4; c++) s2[h][c] = 0.f;

            #pragma unroll
            for (int mi = 0; mi < 4; mi++) {
                #pragma unroll
                for (int e = 0; e < 4; e++) {
                    int h2    = e & 1;
                    int i_loc = wm * 64 + mi * 16 + (e >> 1) * 8 + g;
                    int j_loc = wn * 32 + ni * 8 + 2 * q + h2;
                    float s  = acc[mi][ni][e];
                    float et = __expf(s * inv_t);
                    bool same_t = (sm_ti[i_loc] == sm_tj[j_loc]);
                    if (same_t) {
                        float eb = __expf(s * 2.0f);
                        s2[h2][0] += et;
                        if (sm_bi[i_loc] == sm_bj[j_loc]) s2[h2][2] += eb;
                        else                              s2[h2][3] += eb;
                    } else {
                        s2[h2][1] += et;
                    }
                }
            }
            #pragma unroll
            for (int h2 = 0; h2 < 2; h2++) {
                float a = s2[h2][0], b = s2[h2][1], c = s2[h2][2], d = s2[h2][3];
                #pragma unroll
                for (int o = 4; o <= 16; o <<= 1) {
                    a += __shfl_xor_sync(0xffffffffu, a, o);
                    b += __shfl_xor_sync(0xffffffffu, b, o);
                    c += __shfl_xor_sync(0xffffffffu, c, o);
                    d += __shfl_xor_sync(0xffffffffu, d, o);
                }
                if (g == 0) {
                    int row_loc = wn * 32 + ni * 8 + 2 * q + h2;
                    *(float4*)&red2[(wm * 128 + row_loc) * 4] = make_float4(a, b, c, d);
                }
            }
        }
    }
    __syncthreads();

    if (tid < 128) {
        float a = 0.f, b = 0.f, c = 0.f, d = 0.f;
        #pragma unroll
        for (int v = 0; v < 4; v++) {
            float4 r4 = *(const float4*)&red1[(v * 128 + tid) * 4];
            a += r4.x; b += r4.y; c += r4.z; d += r4.w;
        }
        *(float4*)(g_part + ((size_t)(Ibase + tid) * JSPLIT + J) * 4) = make_float4(a, b, c, d);
    } else if (!diag) {
        int r = tid - 128;
        float4 r0 = *(const float4*)&red2[(r) * 4];
        float4 r1 = *(const float4*)&red2[(128 + r) * 4];
        *(float4*)(g_part + ((size_t)(Jbase + r) * JSPLIT + I) * 4) =
            make_float4(r0.x + r1.x, r0.y + r1.y, r0.z + r1.z, r0.w + r1.w);
    }
}

// ---------------------------------------------------------------------------
// Kernel 3: wide tail (384 blocks x 256 thr; 16 rows/block, 16 thr/row).
// ---------------------------------------------------------------------------
__global__ void k_tail(const int* __restrict__ targets,
                       const int* __restrict__ batch0) {
    __shared__ float sm_lt[16], sm_lb[16];
    __shared__ int   sm_t[16],  sm_b[16];

    const int tid = threadIdx.x;
    const int rl  = tid >> 4;                 // local row 0..15
    const int s16 = tid & 15;                 // split group 0..15
    const int i   = blockIdx.x * 16 + rl;

    float ptv = 0.f, ntv = 0.f, pbv = 0.f, nbv = 0.f;
    const float4* base = (const float4*)(g_part + ((size_t)i * JSPLIT + s16 * 3) * 4);
    #pragma unroll
    for (int s = 0; s < 3; s++) {
        float4 v = base[s];
        ptv += v.x; ntv += v.y; pbv += v.z; nbv += v.w;
    }
    #pragma unroll
    for (int o = 1; o <= 8; o <<= 1) {
        ptv += __shfl_xor_sync(0xffffffffu, ptv, o);
        ntv += __shfl_xor_sync(0xffffffffu, ntv, o);
        pbv += __shfl_xor_sync(0xffffffffu, pbv, o);
        nbv += __shfl_xor_sync(0xffffffffu, nbv, o);
    }

    if (s16 == 0) {
        int tcl = targets[i], bcl = batch0[i];
        int cp  = g_hist_t[tcl];
        bool valid_t = (cp >= 2) && ((NN - cp) >= 1);
        int cpb = g_hist_tb[tcl * NB + bcl];
        int cnb = cp - cpb;
        bool valid_b = (cpb >= 2) && (cnb >= 1);
        sm_lt[rl] = valid_t ? logf((ptv + ntv) / ptv) : 0.0f;
        sm_lb[rl] = valid_b ? (1.0f / logf((pbv + nbv) / pbv)) : 0.0f;
        sm_t[rl]  = tcl;
        sm_b[rl]  = bcl;
    }
    __syncthreads();

    if (tid < NCLS + NB) {
        float s = 0.f;
        if (tid < NCLS) {
            #pragma unroll
            for (int k = 0; k < 16; k++)
                if (sm_t[k] == tid) s += sm_lt[k];
        } else {
            int bc = tid - NCLS;
            #pragma unroll
            for (int k = 0; k < 16; k++)
                if (sm_b[k] == bc) s += sm_lb[k];
        }
        g_blk[blockIdx.x * 32 + tid] = s;
    }
}

// ---------------------------------------------------------------------------
// Kernel 4: final scalar.  256 threads fold 384 block-partials (fixed order).
// ---------------------------------------------------------------------------
__global__ void k_fin(const float* __restrict__ w_t,
                      const float* __restrict__ w_b,
                      float* __restrict__ out) {
    __shared__ float sm[32][8];
    int tid   = threadIdx.x;
    int c     = tid & 31;
    int chunk = tid >> 5;                    // 0..7, 48 blocks each
    float s = 0.f;
    if (c < NCLS + NB) {
        for (int b = chunk * 48; b < chunk * 48 + 48; b++)
            s += g_blk[b * 32 + c];
    }
    sm[c][chunk] = s;
    __syncthreads();

    if (tid < 32) {
        float tot = 0.f;
        #pragma unroll
        for (int k = 0; k < 8; k++) tot += sm[tid][k];

        float contrib = 0.f;
        if (tid < NCLS) {
            int cp = g_hist_t[tid];
            bool valid = (cp >= 2) && ((NN - cp) >= 1);
            float cnt = valid ? (float)cp : 0.f;
            float mean = tot / fmaxf(cnt, 1.0f);
            if (cnt > 0.f) contrib = 0.9f * mean * w_t[tid];
        } else if (tid < NCLS + NB) {
            int bc = tid - NCLS;
            float cnt = 0.f;
            for (int tc = 0; tc < NCLS; tc++) {
                int cpb = g_hist_tb[tc * NB + bc];
                int cnb = g_hist_t[tc] - cpb;
                if ((cpb >= 2) && (cnb >= 1)) cnt += (float)cpb;
            }
            float mean = tot / fmaxf(cnt, 1.0f);
            if (cnt > 0.f) contrib = 0.1f * mean * w_b[bc];
        }
        #pragma unroll
        for (int o = 16; o; o >>= 1) contrib += __shfl_xor_sync(0xffffffffu, contrib, o);
        if (tid == 0) out[0] = contrib;
    }
}

// ---------------------------------------------------------------------------
extern "C" void kernel_launch(void* const* d_in, const int* in_sizes, int n_in,
                              void* d_out, int out_size) {
    const float* x       = (const float*)d_in[0];
    const float* temp    = (const float*)d_in[1];
    const float* w_t     = (const float*)d_in[2];
    const float* w_b     = (const float*)d_in[3];
    const int*   targets = (const int*)d_in[4];
    const int*   batch0  = (const int*)d_in[5];
    float*       out     = (float*)d_out;

    k_norm<<<NN / 16, 256>>>(x);
    k_hist<<<1, 1024>>>(targets, batch0);

    cudaFuncSetAttribute(k_main, cudaFuncAttributeMaxDynamicSharedMemorySize, SMEM_TOTAL);
    k_main<<<NPAIRS, 256, SMEM_TOTAL>>>(temp, targets, batch0);

    k_tail<<<TBLK, 256>>>(targets, batch0);
    k_fin<<<1, 256>>>(w_t, w_b, out);
}

// round 11
// speedup vs baseline: 1.6238x; 1.6238x over previous
#include <cuda_runtime.h>
#include <cuda_fp16.h>
#include <math.h>
#include <stdint.h>

// Problem constants
#define NN    6144
#define DD    128
#define NCLS  20
#define NB    5

#define ITILES 48                     // 6144/128
#define NPAIRS (ITILES*(ITILES+1)/2)  // 1176 tile pairs (I<=J)
#define JSPLIT ITILES

#define TBLK  384                     // k_tail blocks (16 rows each)

// SMEM layout for k_main. Tile rows = 256B (128 fp16), 16B-chunk XOR swizzle.
#define OFF_A    0
#define OFF_B    32768
#define OFF_KI   65536               // packed keys (t*8+b) for I rows, int[128]
#define OFF_KJ   (OFF_KI + 512)      // packed keys for J rows
#define OFF_RED1 OFF_A               // aliased onto dead A tile
#define OFF_RED2 (OFF_A + 8192)
#define SMEM_TOTAL (OFF_KJ + 512)    // ~65.5KB -> 2 CTA/SM

__device__ __forceinline__ uint32_t smem_u32(const void* p) {
    uint32_t a;
    asm("{ .reg .u64 t; cvta.to.shared.u64 t, %1; cvt.u32.u64 %0, t; }" : "=r"(a) : "l"(p));
    return a;
}

#define LDSM_X4(r0, r1, r2, r3, addr) \
    asm volatile("ldmatrix.sync.aligned.m8n8.x4.shared.b16 {%0,%1,%2,%3}, [%4];" \
                 : "=r"(r0), "=r"(r1), "=r"(r2), "=r"(r3) : "r"(addr))

#define MMA_F16(c, a, b0, b1) \
    asm volatile("mma.sync.aligned.m16n8k16.row.col.f32.f16.f16.f32 " \
                 "{%0,%1,%2,%3}, {%4,%5,%6,%7}, {%8,%9}, {%0,%1,%2,%3};" \
                 : "+f"((c)[0]), "+f"((c)[1]), "+f"((c)[2]), "+f"((c)[3]) \
                 : "r"((a)[0]), "r"((a)[1]), "r"((a)[2]), "r"((a)[3]), "r"(b0), "r"(b1))

// ---------------- Scratch (device globals) ----------------
__device__ __half g_h[NN * DD];
__device__ float g_part[NN * JSPLIT * 4];   // [row][split][4] row-major
__device__ int   g_hist_t[NCLS];
__device__ int   g_hist_tb[NCLS * NB];
__device__ float g_blk[TBLK * 32];

// ---------------------------------------------------------------------------
// Kernel 1: normalize + fp16 convert.  Two rows per warp.
// ---------------------------------------------------------------------------
__global__ void k_norm(const float* __restrict__ x) {
    int row0 = blockIdx.x * 16 + (threadIdx.x >> 5) * 2;
    int lane = threadIdx.x & 31;
    float4 v0 = *(const float4*)(x + (size_t)row0 * DD + lane * 4);
    float4 v1 = *(const float4*)(x + (size_t)(row0 + 1) * DD + lane * 4);
    float s0 = v0.x * v0.x + v0.y * v0.y + v0.z * v0.z + v0.w * v0.w;
    float s1 = v1.x * v1.x + v1.y * v1.y + v1.z * v1.z + v1.w * v1.w;
    #pragma unroll
    for (int o = 16; o; o >>= 1) {
        s0 += __shfl_xor_sync(0xffffffffu, s0, o);
        s1 += __shfl_xor_sync(0xffffffffu, s1, o);
    }
    float i0 = 1.0f / fmaxf(sqrtf(s0), 1e-8f);
    float i1 = 1.0f / fmaxf(sqrtf(s1), 1e-8f);
    size_t b0 = (size_t)row0 * DD + lane * 4;
    *(__half2*)(g_h + b0)          = __floats2half2_rn(v0.x * i0, v0.y * i0);
    *(__half2*)(g_h + b0 + 2)      = __floats2half2_rn(v0.z * i0, v0.w * i0);
    *(__half2*)(g_h + b0 + DD)     = __floats2half2_rn(v1.x * i1, v1.y * i1);
    *(__half2*)(g_h + b0 + DD + 2) = __floats2half2_rn(v1.z * i1, v1.w * i1);
}

// ---------------------------------------------------------------------------
// Kernel 1b: histograms (int atomics -> order independent, deterministic).
// ---------------------------------------------------------------------------
__global__ void k_hist(const int* __restrict__ targets, const int* __restrict__ batch0) {
    __shared__ int ht[NCLS], htb[NCLS * NB];
    int tid = threadIdx.x;
    if (tid < NCLS)      ht[tid]  = 0;
    if (tid < NCLS * NB) htb[tid] = 0;
    __syncthreads();
    for (int i = tid; i < NN; i += blockDim.x) {
        int t = targets[i], b = batch0[i];
        atomicAdd(&ht[t], 1);
        atomicAdd(&htb[t * NB + b], 1);
    }
    __syncthreads();
    if (tid < NCLS)      g_hist_t[tid]  = ht[tid];
    if (tid < NCLS * NB) g_hist_tb[tid] = htb[tid];
}

// ---------------------------------------------------------------------------
// Kernel 2: one CTA per tile pair (I,J), I<=J.  fp16 HMMA + single-pass
// BRANCHLESS epilogue with register-resident packed identity keys.
//   key = target*8 + batch (< 160);  x = kI ^ kJ;
//   same_t <=> x < 8;  same_t && same_b <=> x == 0.
//   self handled by zeroing et/eb;  nt = all - st;  nb = sb - pb.
// ---------------------------------------------------------------------------
__device__ __forceinline__ void fill_tile(char* smem, int off,
                                          const __half* __restrict__ src,
                                          int rowbase, int tid) {
    #pragma unroll
    for (int it = 0; it < 8; it++) {
        int lin = it * 256 + tid;
        int n   = lin >> 4;
        int c16 = lin & 15;
        uint4 v = *(const uint4*)(src + (size_t)(rowbase + n) * DD + c16 * 8);
        *(uint4*)(smem + off + n * 256 + ((c16 ^ (n & 7)) << 4)) = v;
    }
}

__global__ void __launch_bounds__(256, 2)
k_main(const float* __restrict__ d_temp,
       const int*   __restrict__ targets,
       const int*   __restrict__ batch0) {
    extern __shared__ char smem[];
    const uint32_t sb = smem_u32(smem);
    const int tid = threadIdx.x;
    const int L   = tid & 31;
    const int w   = tid >> 5;
    const int wm  = w & 1;
    const int wn  = w >> 1;

    int p = blockIdx.x, I = 0;
    while (p >= ITILES - I) { p -= ITILES - I; I++; }
    const int J = I + p;
    const int Ibase = I * 128;
    const int Jbase = J * 128;
    const bool diag = (I == J);

    int*   sm_ki = (int*)(smem + OFF_KI);
    int*   sm_kj = (int*)(smem + OFF_KJ);
    float* red1  = (float*)(smem + OFF_RED1);
    float* red2  = (float*)(smem + OFF_RED2);

    const float t     = fminf(fmaxf(d_temp[0], 0.1f), 1.0f);
    const float inv_t = 1.0f / t;

    fill_tile(smem, OFF_A, g_h, Ibase, tid);
    fill_tile(smem, OFF_B, g_h, Jbase, tid);
    if (tid < 128) {
        sm_ki[tid] = targets[Ibase + tid] * 8 + batch0[Ibase + tid];
    } else {
        int r = tid - 128;
        sm_kj[r] = targets[Jbase + r] * 8 + batch0[Jbase + r];
    }
    __syncthreads();

    const int la15 = L & 15;
    const int l4   = L >> 4;
    const int lb7  = (L & 7) + ((L >> 4) << 3);
    const int lb1  = (L >> 3) & 1;

    float acc[4][4][4];
    #pragma unroll
    for (int mi = 0; mi < 4; mi++)
        #pragma unroll
        for (int ni = 0; ni < 4; ni++)
            #pragma unroll
            for (int e = 0; e < 4; e++) acc[mi][ni][e] = 0.f;

    #pragma unroll
    for (int ks = 0; ks < 8; ks++) {
        uint32_t a[4][4], b[2][4];
        #pragma unroll
        for (int mi = 0; mi < 4; mi++) {
            int rowA = wm * 64 + mi * 16 + la15;
            uint32_t ad = sb + OFF_A + rowA * 256 + (((ks * 2 + l4) ^ (rowA & 7)) << 4);
            LDSM_X4(a[mi][0], a[mi][1], a[mi][2], a[mi][3], ad);
        }
        #pragma unroll
        for (int np = 0; np < 2; np++) {
            int rowB = wn * 32 + np * 16 + lb7;
            uint32_t bd = sb + OFF_B + rowB * 256 + (((ks * 2 + lb1) ^ (rowB & 7)) << 4);
            LDSM_X4(b[np][0], b[np][1], b[np][2], b[np][3], bd);
        }
        #pragma unroll
        for (int mi = 0; mi < 4; mi++)
            #pragma unroll
            for (int ni = 0; ni < 4; ni++)
                MMA_F16(acc[mi][ni], a[mi],
                        b[ni >> 1][(ni & 1) * 2], b[ni >> 1][(ni & 1) * 2 + 1]);
    }

    const int g = L >> 2, q = L & 3;

    // Pack this thread's 8 i-keys and 8 j-keys into registers.
    uint32_t kIa[2] = {0u, 0u}, kJa[2] = {0u, 0u};
    #pragma unroll
    for (int pk = 0; pk < 8; pk++) {
        int row = wm * 64 + (pk >> 1) * 16 + (pk & 1) * 8 + g;
        kIa[pk >> 2] |= ((uint32_t)sm_ki[row]) << ((pk & 3) * 8);
        int col = wn * 32 + (pk >> 1) * 8 + 2 * q + (pk & 1);
        kJa[pk >> 2] |= ((uint32_t)sm_kj[col]) << ((pk & 3) * 8);
    }
    __syncthreads();   // LDSM + key reads of A-region done; red buffers safe

    // Side-2 running sums (rows of J), index pj = ni*2 + l.
    float all2[8], st2[8], sb2[8], pb2[8];
    #pragma unroll
    for (int k = 0; k < 8; k++) { all2[k]=st2[k]=sb2[k]=pb2[k]=0.f; }

    #pragma unroll
    for (int mi = 0; mi < 4; mi++) {
        float a1[2] = {0.f, 0.f}, s1[2] = {0.f, 0.f};
        float b1[2] = {0.f, 0.f}, p1[2] = {0.f, 0.f};

        #pragma unroll
        for (int ni = 0; ni < 4; ni++) {
            #pragma unroll
            for (int e = 0; e < 4; e++) {
                const int h  = e >> 1, l = e & 1;
                const int pi = mi * 2 + h, pj = ni * 2 + l;
                uint32_t kib = (kIa[pi >> 2] >> ((pi & 3) * 8)) & 0xFFu;
                uint32_t kjb = (kJa[pj >> 2] >> ((pj & 3) * 8)) & 0xFFu;
                uint32_t x = kib ^ kjb;
                bool same_t = (x < 8u);
                bool eq     = (x == 0u);
                bool self   = diag &&
                    ((wm * 64 + mi * 16 + h * 8 + g) == (wn * 32 + ni * 8 + 2 * q + l));
                float s  = acc[mi][ni][e];
                float et = __expf(s * inv_t);
                float eb = __expf(s * 2.0f);     // 1/TEMP_BATCH
                et = self ? 0.f : et;
                eb = self ? 0.f : eb;
                float et_st = same_t ? et : 0.f;
                float eb_st = same_t ? eb : 0.f;
                float eb_eq = eq     ? eb : 0.f;
                a1[h] += et;   s1[h] += et_st;  b1[h] += eb_st;  p1[h] += eb_eq;
                all2[pj] += et; st2[pj] += et_st; sb2[pj] += eb_st; pb2[pj] += eb_eq;
            }
        }
        // Finalize + reduce this mi-slice's 2 rows over the 4 q-lanes.
        #pragma unroll
        for (int h = 0; h < 2; h++) {
            float pt = s1[h];
            float nt = a1[h] - s1[h];
            float pb = p1[h];
            float nb = b1[h] - p1[h];
            #pragma unroll
            for (int o = 1; o <= 2; o <<= 1) {
                pt += __shfl_xor_sync(0xffffffffu, pt, o);
                nt += __shfl_xor_sync(0xffffffffu, nt, o);
                pb += __shfl_xor_sync(0xffffffffu, pb, o);
                nb += __shfl_xor_sync(0xffffffffu, nb, o);
            }
            if (q == 0) {
                int row_loc = wm * 64 + mi * 16 + h * 8 + g;
                *(float4*)&red1[(wn * 128 + row_loc) * 4] = make_float4(pt, nt, pb, nb);
            }
        }
    }

    // Side-2: finalize + reduce over g lanes (offsets 4,8,16), then wm via smem.
    if (!diag) {
        #pragma unroll
        for (int k = 0; k < 8; k++) {
            float pt = st2[k];
            float nt = all2[k] - st2[k];
            float pb = pb2[k];
            float nb = sb2[k] - pb2[k];
            #pragma unroll
            for (int o = 4; o <= 16; o <<= 1) {
                pt += __shfl_xor_sync(0xffffffffu, pt, o);
                nt += __shfl_xor_sync(0xffffffffu, nt, o);
                pb += __shfl_xor_sync(0xffffffffu, pb, o);
                nb += __shfl_xor_sync(0xffffffffu, nb, o);
            }
            if (g == 0) {
                int row_loc = wn * 32 + (k >> 1) * 8 + 2 * q + (k & 1);
                *(float4*)&red2[(wm * 128 + row_loc) * 4] = make_float4(pt, nt, pb, nb);
            }
        }
    }
    __syncthreads();

    if (tid < 128) {
        float a = 0.f, b = 0.f, c = 0.f, d = 0.f;
        #pragma unroll
        for (int v = 0; v < 4; v++) {
            float4 r4 = *(const float4*)&red1[(v * 128 + tid) * 4];
            a += r4.x; b += r4.y; c += r4.z; d += r4.w;
        }
        *(float4*)(g_part + ((size_t)(Ibase + tid) * JSPLIT + J) * 4) = make_float4(a, b, c, d);
    } else if (!diag) {
        int r = tid - 128;
        float4 r0 = *(const float4*)&red2[(r) * 4];
        float4 r1 = *(const float4*)&red2[(128 + r) * 4];
        *(float4*)(g_part + ((size_t)(Jbase + r) * JSPLIT + I) * 4) =
            make_float4(r0.x + r1.x, r0.y + r1.y, r0.z + r1.z, r0.w + r1.w);
    }
}

// ---------------------------------------------------------------------------
// Kernel 3: wide tail (384 blocks x 256 thr; 16 rows/block, 16 thr/row).
// ---------------------------------------------------------------------------
__global__ void k_tail(const int* __restrict__ targets,
                       const int* __restrict__ batch0) {
    __shared__ float sm_lt[16], sm_lb[16];
    __shared__ int   sm_t[16],  sm_b[16];

    const int tid = threadIdx.x;
    const int rl  = tid >> 4;
    const int s16 = tid & 15;
    const int i   = blockIdx.x * 16 + rl;

    float ptv = 0.f, ntv = 0.f, pbv = 0.f, nbv = 0.f;
    const float4* base = (const float4*)(g_part + ((size_t)i * JSPLIT + s16 * 3) * 4);
    #pragma unroll
    for (int s = 0; s < 3; s++) {
        float4 v = base[s];
        ptv += v.x; ntv += v.y; pbv += v.z; nbv += v.w;
    }
    #pragma unroll
    for (int o = 1; o <= 8; o <<= 1) {
        ptv += __shfl_xor_sync(0xffffffffu, ptv, o);
        ntv += __shfl_xor_sync(0xffffffffu, ntv, o);
        pbv += __shfl_xor_sync(0xffffffffu, pbv, o);
        nbv += __shfl_xor_sync(0xffffffffu, nbv, o);
    }

    if (s16 == 0) {
        int tcl = targets[i], bcl = batch0[i];
        int cp  = g_hist_t[tcl];
        bool valid_t = (cp >= 2) && ((NN - cp) >= 1);
        int cpb = g_hist_tb[tcl * NB + bcl];
        int cnb = cp - cpb;
        bool valid_b = (cpb >= 2) && (cnb >= 1);
        sm_lt[rl] = valid_t ? logf((ptv + ntv) / ptv) : 0.0f;
        sm_lb[rl] = valid_b ? (1.0f / logf((pbv + nbv) / pbv)) : 0.0f;
        sm_t[rl]  = tcl;
        sm_b[rl]  = bcl;
    }
    __syncthreads();

    if (tid < NCLS + NB) {
        float s = 0.f;
        if (tid < NCLS) {
            #pragma unroll
            for (int k = 0; k < 16; k++)
                if (sm_t[k] == tid) s += sm_lt[k];
        } else {
            int bc = tid - NCLS;
            #pragma unroll
            for (int k = 0; k < 16; k++)
                if (sm_b[k] == bc) s += sm_lb[k];
        }
        g_blk[blockIdx.x * 32 + tid] = s;
    }
}

// ---------------------------------------------------------------------------
// Kernel 4: final scalar.  256 threads fold 384 block-partials (fixed order).
// ---------------------------------------------------------------------------
__global__ void k_fin(const float* __restrict__ w_t,
                      const float* __restrict__ w_b,
                      float* __restrict__ out) {
    __shared__ float sm[32][8];
    int tid   = threadIdx.x;
    int c     = tid & 31;
    int chunk = tid >> 5;
    float s = 0.f;
    if (c < NCLS + NB) {
        for (int b = chunk * 48; b < chunk * 48 + 48; b++)
            s += g_blk[b * 32 + c];
    }
    sm[c][chunk] = s;
    __syncthreads();

    if (tid < 32) {
        float tot = 0.f;
        #pragma unroll
        for (int k = 0; k < 8; k++) tot += sm[tid][k];

        float contrib = 0.f;
        if (tid < NCLS) {
            int cp = g_hist_t[tid];
            bool valid = (cp >= 2) && ((NN - cp) >= 1);
            float cnt = valid ? (float)cp : 0.f;
            float mean = tot / fmaxf(cnt, 1.0f);
            if (cnt > 0.f) contrib = 0.9f * mean * w_t[tid];
        } else if (tid < NCLS + NB) {
            int bc = tid - NCLS;
            float cnt = 0.f;
            for (int tc = 0; tc < NCLS; tc++) {
                int cpb = g_hist_tb[tc * NB + bc];
                int cnb = g_hist_t[tc] - cpb;
                if ((cpb >= 2) && (cnb >= 1)) cnt += (float)cpb;
            }
            float mean = tot / fmaxf(cnt, 1.0f);
            if (cnt > 0.f) contrib = 0.1f * mean * w_b[bc];
        }
        #pragma unroll
        for (int o = 16; o; o >>= 1) contrib += __shfl_xor_sync(0xffffffffu, contrib, o);
        if (tid == 0) out[0] = contrib;
    }
}

// ---------------------------------------------------------------------------
extern "C" void kernel_launch(void* const* d_in, const int* in_sizes, int n_in,
                              void* d_out, int out_size) {
    const float* x       = (const float*)d_in[0];
    const float* temp    = (const float*)d_in[1];
    const float* w_t     = (const float*)d_in[2];
    const float* w_b     = (const float*)d_in[3];
    const int*   targets = (const int*)d_in[4];
    const int*   batch0  = (const int*)d_in[5];
    float*       out     = (float*)d_out;

    k_norm<<<NN / 16, 256>>>(x);
    k_hist<<<1, 1024>>>(targets, batch0);

    cudaFuncSetAttribute(k_main, cudaFuncAttributeMaxDynamicSharedMemorySize, SMEM_TOTAL);
    k_main<<<NPAIRS, 256, SMEM_TOTAL>>>(temp, targets, batch0);

    k_tail<<<TBLK, 256>>>(targets, batch0);
    k_fin<<<1, 256>>>(w_t, w_b, out);
}

// round 12
// speedup vs baseline: 1.7540x; 1.0802x over previous
#include <cuda_runtime.h>
#include <cuda_fp16.h>
#include <math.h>
#include <stdint.h>

// Problem constants
#define NN    6144
#define DD    128
#define NCLS  20
#define NB    5

#define ITILES 48                     // 6144/128
#define NPAIRS (ITILES*(ITILES+1)/2)  // 1176 tile pairs (I<=J)
#define JSPLIT ITILES

#define TBLK  384                     // k_tail blocks (16 rows each)
#define NORMB 384                     // norm blocks inside k_prep

// SMEM layout for k_main. Tile rows = 256B (128 fp16), 16B-chunk XOR swizzle.
#define OFF_A    0
#define OFF_B    32768
#define OFF_KI   65536
#define OFF_KJ   (OFF_KI + 512)
#define OFF_RED1 OFF_A               // aliased onto dead A tile
#define OFF_RED2 (OFF_A + 8192)
#define SMEM_TOTAL (OFF_KJ + 512)    // ~65.5KB -> 2 CTA/SM

__device__ __forceinline__ uint32_t smem_u32(const void* p) {
    uint32_t a;
    asm("{ .reg .u64 t; cvta.to.shared.u64 t, %1; cvt.u32.u64 %0, t; }" : "=r"(a) : "l"(p));
    return a;
}

#define LDSM_X4(r0, r1, r2, r3, addr) \
    asm volatile("ldmatrix.sync.aligned.m8n8.x4.shared.b16 {%0,%1,%2,%3}, [%4];" \
                 : "=r"(r0), "=r"(r1), "=r"(r2), "=r"(r3) : "r"(addr))

#define MMA_F16(c, a, b0, b1) \
    asm volatile("mma.sync.aligned.m16n8k16.row.col.f32.f16.f16.f32 " \
                 "{%0,%1,%2,%3}, {%4,%5,%6,%7}, {%8,%9}, {%0,%1,%2,%3};" \
                 : "+f"((c)[0]), "+f"((c)[1]), "+f"((c)[2]), "+f"((c)[3]) \
                 : "r"((a)[0]), "r"((a)[1]), "r"((a)[2]), "r"((a)[3]), "r"(b0), "r"(b1))

// ---------------- Scratch (device globals) ----------------
__device__ __half g_h[NN * DD];
__device__ float g_part[NN * JSPLIT * 4];   // [row][split][4]
__device__ int   g_hist_t[NCLS];
__device__ int   g_hist_tb[NCLS * NB];
__device__ float g_blk[TBLK * 32];

// ---------------------------------------------------------------------------
// Kernel 1: prep = normalize+fp16 convert (blocks 0..383) + histogram (block 384).
// ---------------------------------------------------------------------------
__global__ void k_prep(const float* __restrict__ x,
                       const int* __restrict__ targets,
                       const int* __restrict__ batch0) {
    if (blockIdx.x < NORMB) {
        int row0 = blockIdx.x * 16 + (threadIdx.x >> 5) * 2;
        int lane = threadIdx.x & 31;
        float4 v0 = *(const float4*)(x + (size_t)row0 * DD + lane * 4);
        float4 v1 = *(const float4*)(x + (size_t)(row0 + 1) * DD + lane * 4);
        float s0 = v0.x * v0.x + v0.y * v0.y + v0.z * v0.z + v0.w * v0.w;
        float s1 = v1.x * v1.x + v1.y * v1.y + v1.z * v1.z + v1.w * v1.w;
        #pragma unroll
        for (int o = 16; o; o >>= 1) {
            s0 += __shfl_xor_sync(0xffffffffu, s0, o);
            s1 += __shfl_xor_sync(0xffffffffu, s1, o);
        }
        float i0 = 1.0f / fmaxf(sqrtf(s0), 1e-8f);
        float i1 = 1.0f / fmaxf(sqrtf(s1), 1e-8f);
        size_t b0 = (size_t)row0 * DD + lane * 4;
        *(__half2*)(g_h + b0)          = __floats2half2_rn(v0.x * i0, v0.y * i0);
        *(__half2*)(g_h + b0 + 2)      = __floats2half2_rn(v0.z * i0, v0.w * i0);
        *(__half2*)(g_h + b0 + DD)     = __floats2half2_rn(v1.x * i1, v1.y * i1);
        *(__half2*)(g_h + b0 + DD + 2) = __floats2half2_rn(v1.z * i1, v1.w * i1);
    } else {
        __shared__ int ht[NCLS], htb[NCLS * NB];
        int tid = threadIdx.x;
        if (tid < NCLS)      ht[tid]  = 0;
        if (tid < NCLS * NB) htb[tid] = 0;
        __syncthreads();
        for (int i = tid; i < NN; i += blockDim.x) {
            int t = targets[i], b = batch0[i];
            atomicAdd(&ht[t], 1);
            atomicAdd(&htb[t * NB + b], 1);
        }
        __syncthreads();
        if (tid < NCLS)      g_hist_t[tid]  = ht[tid];
        if (tid < NCLS * NB) g_hist_tb[tid] = htb[tid];
    }
}

// ---------------------------------------------------------------------------
// Templated epilogue: DIAG = tile is on the diagonal (self-exclusion needed),
// FAST = inv_t == 4 exactly (t == 0.25): et = eb*eb with eb = exp(2s).
// ---------------------------------------------------------------------------
template <bool DIAG, bool FAST>
__device__ __forceinline__ void epilogue(
    const float (&acc)[4][4][4],
    const uint32_t (&kIa)[2], const uint32_t* kj8,
    float inv_t, float* red1, float* red2,
    int wm, int wn, int g, int q)
{
    float all2[8], st2[8], sb2[8], pb2[8];
    #pragma unroll
    for (int k = 0; k < 8; k++) { all2[k]=st2[k]=sb2[k]=pb2[k]=0.f; }

    #pragma unroll
    for (int mi = 0; mi < 4; mi++) {
        float a1[2] = {0.f, 0.f}, s1[2] = {0.f, 0.f};
        float b1[2] = {0.f, 0.f}, p1[2] = {0.f, 0.f};
        uint32_t kib[2];
        #pragma unroll
        for (int h = 0; h < 2; h++) {
            int pi = mi * 2 + h;
            kib[h] = (kIa[pi >> 2] >> ((pi & 3) * 8)) & 0xFFu;
        }

        #pragma unroll
        for (int ni = 0; ni < 4; ni++) {
            #pragma unroll
            for (int e = 0; e < 4; e++) {
                const int h  = e >> 1, l = e & 1;
                const int pj = ni * 2 + l;
                uint32_t x = kib[h] ^ kj8[pj];
                bool same_t = (x < 8u);
                bool eq     = (x == 0u);
                float s  = acc[mi][ni][e];
                float eb, et;
                if (FAST) { eb = __expf(s + s); et = eb * eb; }
                else      { eb = __expf(s + s); et = __expf(s * inv_t); }
                if (DIAG) {
                    bool self = ((wm * 64 + mi * 16 + h * 8 + g) ==
                                 (wn * 32 + ni * 8 + 2 * q + l));
                    et = self ? 0.f : et;
                    eb = self ? 0.f : eb;
                }
                float et_st = same_t ? et : 0.f;
                float eb_st = same_t ? eb : 0.f;
                float eb_eq = eq     ? eb : 0.f;
                a1[h] += et;    s1[h] += et_st;   b1[h] += eb_st;   p1[h] += eb_eq;
                all2[pj] += et; st2[pj] += et_st; sb2[pj] += eb_st; pb2[pj] += eb_eq;
            }
        }
        #pragma unroll
        for (int h = 0; h < 2; h++) {
            float pt = s1[h];
            float nt = a1[h] - s1[h];
            float pb = p1[h];
            float nb = b1[h] - p1[h];
            #pragma unroll
            for (int o = 1; o <= 2; o <<= 1) {
                pt += __shfl_xor_sync(0xffffffffu, pt, o);
                nt += __shfl_xor_sync(0xffffffffu, nt, o);
                pb += __shfl_xor_sync(0xffffffffu, pb, o);
                nb += __shfl_xor_sync(0xffffffffu, nb, o);
            }
            if (q == 0) {
                int row_loc = wm * 64 + mi * 16 + h * 8 + g;
                *(float4*)&red1[(wn * 128 + row_loc) * 4] = make_float4(pt, nt, pb, nb);
            }
        }
    }

    if (!DIAG) {
        #pragma unroll
        for (int k = 0; k < 8; k++) {
            float pt = st2[k];
            float nt = all2[k] - st2[k];
            float pb = pb2[k];
            float nb = sb2[k] - pb2[k];
            #pragma unroll
            for (int o = 4; o <= 16; o <<= 1) {
                pt += __shfl_xor_sync(0xffffffffu, pt, o);
                nt += __shfl_xor_sync(0xffffffffu, nt, o);
                pb += __shfl_xor_sync(0xffffffffu, pb, o);
                nb += __shfl_xor_sync(0xffffffffu, nb, o);
            }
            if (g == 0) {
                int row_loc = wn * 32 + (k >> 1) * 8 + 2 * q + (k & 1);
                *(float4*)&red2[(wm * 128 + row_loc) * 4] = make_float4(pt, nt, pb, nb);
            }
        }
    }
}

// ---------------------------------------------------------------------------
// Kernel 2: one CTA per tile pair (I,J), I<=J.  fp16 HMMA + fused epilogue.
// ---------------------------------------------------------------------------
__device__ __forceinline__ void fill_tile(char* smem, int off,
                                          const __half* __restrict__ src,
                                          int rowbase, int tid) {
    #pragma unroll
    for (int it = 0; it < 8; it++) {
        int lin = it * 256 + tid;
        int n   = lin >> 4;
        int c16 = lin & 15;
        uint4 v = *(const uint4*)(src + (size_t)(rowbase + n) * DD + c16 * 8);
        *(uint4*)(smem + off + n * 256 + ((c16 ^ (n & 7)) << 4)) = v;
    }
}

__global__ void __launch_bounds__(256, 2)
k_main(const float* __restrict__ d_temp,
       const int*   __restrict__ targets,
       const int*   __restrict__ batch0) {
    extern __shared__ char smem[];
    const uint32_t sb = smem_u32(smem);
    const int tid = threadIdx.x;
    const int L   = tid & 31;
    const int w   = tid >> 5;
    const int wm  = w & 1;
    const int wn  = w >> 1;

    int p = blockIdx.x, I = 0;
    while (p >= ITILES - I) { p -= ITILES - I; I++; }
    const int J = I + p;
    const int Ibase = I * 128;
    const int Jbase = J * 128;
    const bool diag = (I == J);

    int*   sm_ki = (int*)(smem + OFF_KI);
    int*   sm_kj = (int*)(smem + OFF_KJ);
    float* red1  = (float*)(smem + OFF_RED1);
    float* red2  = (float*)(smem + OFF_RED2);

    const float t     = fminf(fmaxf(d_temp[0], 0.1f), 1.0f);
    const float inv_t = 1.0f / t;
    const bool  fast  = (inv_t == 4.0f);

    fill_tile(smem, OFF_A, g_h, Ibase, tid);
    fill_tile(smem, OFF_B, g_h, Jbase, tid);
    if (tid < 128) {
        sm_ki[tid] = targets[Ibase + tid] * 8 + batch0[Ibase + tid];
    } else {
        int r = tid - 128;
        sm_kj[r] = targets[Jbase + r] * 8 + batch0[Jbase + r];
    }
    __syncthreads();

    const int la15 = L & 15;
    const int l4   = L >> 4;
    const int lb7  = (L & 7) + ((L >> 4) << 3);
    const int lb1  = (L >> 3) & 1;

    float acc[4][4][4];
    #pragma unroll
    for (int mi = 0; mi < 4; mi++)
        #pragma unroll
        for (int ni = 0; ni < 4; ni++)
            #pragma unroll
            for (int e = 0; e < 4; e++) acc[mi][ni][e] = 0.f;

    #pragma unroll
    for (int ks = 0; ks < 8; ks++) {
        uint32_t a[4][4], b[2][4];
        #pragma unroll
        for (int mi = 0; mi < 4; mi++) {
            int rowA = wm * 64 + mi * 16 + la15;
            uint32_t ad = sb + OFF_A + rowA * 256 + (((ks * 2 + l4) ^ (rowA & 7)) << 4);
            LDSM_X4(a[mi][0], a[mi][1], a[mi][2], a[mi][3], ad);
        }
        #pragma unroll
        for (int np = 0; np < 2; np++) {
            int rowB = wn * 32 + np * 16 + lb7;
            uint32_t bd = sb + OFF_B + rowB * 256 + (((ks * 2 + lb1) ^ (rowB & 7)) << 4);
            LDSM_X4(b[np][0], b[np][1], b[np][2], b[np][3], bd);
        }
        #pragma unroll
        for (int mi = 0; mi < 4; mi++)
            #pragma unroll
            for (int ni = 0; ni < 4; ni++)
                MMA_F16(acc[mi][ni], a[mi],
                        b[ni >> 1][(ni & 1) * 2], b[ni >> 1][(ni & 1) * 2 + 1]);
    }

    const int g = L >> 2, q = L & 3;

    // Pack i-keys (bytes in 2 regs); j-keys extracted to 8 regs.
    uint32_t kIa[2] = {0u, 0u};
    uint32_t kj8[8];
    #pragma unroll
    for (int pk = 0; pk < 8; pk++) {
        int row = wm * 64 + (pk >> 1) * 16 + (pk & 1) * 8 + g;
        kIa[pk >> 2] |= ((uint32_t)sm_ki[row]) << ((pk & 3) * 8);
        int col = wn * 32 + (pk >> 1) * 8 + 2 * q + (pk & 1);
        kj8[pk] = (uint32_t)sm_kj[col];
    }
    __syncthreads();   // LDSM + key reads of A-region done; red buffers safe

    if (diag) {
        if (fast) epilogue<true,  true >(acc, kIa, kj8, inv_t, red1, red2, wm, wn, g, q);
        else      epilogue<true,  false>(acc, kIa, kj8, inv_t, red1, red2, wm, wn, g, q);
    } else {
        if (fast) epilogue<false, true >(acc, kIa, kj8, inv_t, red1, red2, wm, wn, g, q);
        else      epilogue<false, false>(acc, kIa, kj8, inv_t, red1, red2, wm, wn, g, q);
    }
    __syncthreads();

    if (tid < 128) {
        float a = 0.f, b = 0.f, c = 0.f, d = 0.f;
        #pragma unroll
        for (int v = 0; v < 4; v++) {
            float4 r4 = *(const float4*)&red1[(v * 128 + tid) * 4];
            a += r4.x; b += r4.y; c += r4.z; d += r4.w;
        }
        *(float4*)(g_part + ((size_t)(Ibase + tid) * JSPLIT + J) * 4) = make_float4(a, b, c, d);
    } else if (!diag) {
        int r = tid - 128;
        float4 r0 = *(const float4*)&red2[(r) * 4];
        float4 r1 = *(const float4*)&red2[(128 + r) * 4];
        *(float4*)(g_part + ((size_t)(Jbase + r) * JSPLIT + I) * 4) =
            make_float4(r0.x + r1.x, r0.y + r1.y, r0.z + r1.z, r0.w + r1.w);
    }
}

// ---------------------------------------------------------------------------
// Kernel 3: wide tail (384 blocks x 256 thr; 16 rows/block, 16 thr/row).
// ---------------------------------------------------------------------------
__global__ void k_tail(const int* __restrict__ targets,
                       const int* __restrict__ batch0) {
    __shared__ float sm_lt[16], sm_lb[16];
    __shared__ int   sm_t[16],  sm_b[16];

    const int tid = threadIdx.x;
    const int rl  = tid >> 4;
    const int s16 = tid & 15;
    const int i   = blockIdx.x * 16 + rl;

    float ptv = 0.f, ntv = 0.f, pbv = 0.f, nbv = 0.f;
    const float4* base = (const float4*)(g_part + ((size_t)i * JSPLIT + s16 * 3) * 4);
    #pragma unroll
    for (int s = 0; s < 3; s++) {
        float4 v = base[s];
        ptv += v.x; ntv += v.y; pbv += v.z; nbv += v.w;
    }
    #pragma unroll
    for (int o = 1; o <= 8; o <<= 1) {
        ptv += __shfl_xor_sync(0xffffffffu, ptv, o);
        ntv += __shfl_xor_sync(0xffffffffu, ntv, o);
        pbv += __shfl_xor_sync(0xffffffffu, pbv, o);
        nbv += __shfl_xor_sync(0xffffffffu, nbv, o);
    }

    if (s16 == 0) {
        int tcl = targets[i], bcl = batch0[i];
        int cp  = g_hist_t[tcl];
        bool valid_t = (cp >= 2) && ((NN - cp) >= 1);
        int cpb = g_hist_tb[tcl * NB + bcl];
        int cnb = cp - cpb;
        bool valid_b = (cpb >= 2) && (cnb >= 1);
        sm_lt[rl] = valid_t ? logf((ptv + ntv) / ptv) : 0.0f;
        sm_lb[rl] = valid_b ? (1.0f / logf((pbv + nbv) / pbv)) : 0.0f;
        sm_t[rl]  = tcl;
        sm_b[rl]  = bcl;
    }
    __syncthreads();

    if (tid < NCLS + NB) {
        float s = 0.f;
        if (tid < NCLS) {
            #pragma unroll
            for (int k = 0; k < 16; k++)
                if (sm_t[k] == tid) s += sm_lt[k];
        } else {
            int bc = tid - NCLS;
            #pragma unroll
            for (int k = 0; k < 16; k++)
                if (sm_b[k] == bc) s += sm_lb[k];
        }
        g_blk[blockIdx.x * 32 + tid] = s;
    }
}

// ---------------------------------------------------------------------------
// Kernel 4: final scalar.  256 threads fold 384 block-partials (fixed order).
// ---------------------------------------------------------------------------
__global__ void k_fin(const float* __restrict__ w_t,
                      const float* __restrict__ w_b,
                      float* __restrict__ out) {
    __shared__ float sm[32][8];
    int tid   = threadIdx.x;
    int c     = tid & 31;
    int chunk = tid >> 5;
    float s = 0.f;
    if (c < NCLS + NB) {
        for (int b = chunk * 48; b < chunk * 48 + 48; b++)
            s += g_blk[b * 32 + c];
    }
    sm[c][chunk] = s;
    __syncthreads();

    if (tid < 32) {
        float tot = 0.f;
        #pragma unroll
        for (int k = 0; k < 8; k++) tot += sm[tid][k];

        float contrib = 0.f;
        if (tid < NCLS) {
            int cp = g_hist_t[tid];
            bool valid = (cp >= 2) && ((NN - cp) >= 1);
            float cnt = valid ? (float)cp : 0.f;
            float mean = tot / fmaxf(cnt, 1.0f);
            if (cnt > 0.f) contrib = 0.9f * mean * w_t[tid];
        } else if (tid < NCLS + NB) {
            int bc = tid - NCLS;
            float cnt = 0.f;
            for (int tc = 0; tc < NCLS; tc++) {
                int cpb = g_hist_tb[tc * NB + bc];
                int cnb = g_hist_t[tc] - cpb;
                if ((cpb >= 2) && (cnb >= 1)) cnt += (float)cpb;
            }
            float mean = tot / fmaxf(cnt, 1.0f);
            if (cnt > 0.f) contrib = 0.1f * mean * w_b[bc];
        }
        #pragma unroll
        for (int o = 16; o; o >>= 1) contrib += __shfl_xor_sync(0xffffffffu, contrib, o);
        if (tid == 0) out[0] = contrib;
    }
}

// ---------------------------------------------------------------------------
extern "C" void kernel_launch(void* const* d_in, const int* in_sizes, int n_in,
                              void* d_out, int out_size) {
    const float* x       = (const float*)d_in[0];
    const float* temp    = (const float*)d_in[1];
    const float* w_t     = (const float*)d_in[2];
    const float* w_b     = (const float*)d_in[3];
    const int*   targets = (const int*)d_in[4];
    const int*   batch0  = (const int*)d_in[5];
    float*       out     = (float*)d_out;

    k_prep<<<NORMB + 1, 256>>>(x, targets, batch0);

    cudaFuncSetAttribute(k_main, cudaFuncAttributeMaxDynamicSharedMemorySize, SMEM_TOTAL);
    k_main<<<NPAIRS, 256, SMEM_TOTAL>>>(temp, targets, batch0);

    k_tail<<<TBLK, 256>>>(targets, batch0);
    k_fin<<<1, 256>>>(w_t, w_b, out);
}

// round 13
// speedup vs baseline: 1.7646x; 1.0061x over previous
#include <cuda_runtime.h>
#include <cuda_fp16.h>
#include <math.h>
#include <stdint.h>

// Problem constants
#define NN    6144
#define DD    128
#define NCLS  20
#define NB    5

#define ITILES 48                     // 6144/128
#define NPAIRS (ITILES*(ITILES+1)/2)  // 1176 tile pairs (I<=J)
#define JSPLIT ITILES

#define TBLK  768                     // k_tail blocks (8 rows each)
#define NORMB 384                     // norm blocks inside k_prep

// SMEM layout for k_main. Tile rows = 256B (128 fp16), 16B-chunk XOR swizzle.
#define OFF_A    0
#define OFF_B    32768
#define OFF_KI   65536
#define OFF_KJ   (OFF_KI + 512)
#define OFF_RED1 OFF_A               // aliased onto dead A tile
#define OFF_RED2 (OFF_A + 8192)
#define SMEM_TOTAL (OFF_KJ + 512)    // ~65.5KB -> 2 CTA/SM

__device__ __forceinline__ uint32_t smem_u32(const void* p) {
    uint32_t a;
    asm("{ .reg .u64 t; cvta.to.shared.u64 t, %1; cvt.u32.u64 %0, t; }" : "=r"(a) : "l"(p));
    return a;
}

#define LDSM_X4(r0, r1, r2, r3, addr) \
    asm volatile("ldmatrix.sync.aligned.m8n8.x4.shared.b16 {%0,%1,%2,%3}, [%4];" \
                 : "=r"(r0), "=r"(r1), "=r"(r2), "=r"(r3) : "r"(addr))

#define MMA_F16(c, a, b0, b1) \
    asm volatile("mma.sync.aligned.m16n8k16.row.col.f32.f16.f16.f32 " \
                 "{%0,%1,%2,%3}, {%4,%5,%6,%7}, {%8,%9}, {%0,%1,%2,%3};" \
                 : "+f"((c)[0]), "+f"((c)[1]), "+f"((c)[2]), "+f"((c)[3]) \
                 : "r"((a)[0]), "r"((a)[1]), "r"((a)[2]), "r"((a)[3]), "r"(b0), "r"(b1))

// ---------------- Scratch (device globals) ----------------
__device__ __half g_h[NN * DD];
__device__ float g_part[NN * JSPLIT * 4];   // [row][split][4]
__device__ int   g_hist_t[NCLS];
__device__ int   g_hist_tb[NCLS * NB];
__device__ float g_blk[32 * TBLK];          // class-major: [cls][block]

// ---------------------------------------------------------------------------
// Kernel 1: prep = normalize+fp16 (blocks 0..383) + histogram (block 384).
// ---------------------------------------------------------------------------
__global__ void k_prep(const float* __restrict__ x,
                       const int* __restrict__ targets,
                       const int* __restrict__ batch0) {
    if (blockIdx.x < NORMB) {
        int row0 = blockIdx.x * 16 + (threadIdx.x >> 5) * 2;
        int lane = threadIdx.x & 31;
        float4 v0 = *(const float4*)(x + (size_t)row0 * DD + lane * 4);
        float4 v1 = *(const float4*)(x + (size_t)(row0 + 1) * DD + lane * 4);
        float s0 = v0.x * v0.x + v0.y * v0.y + v0.z * v0.z + v0.w * v0.w;
        float s1 = v1.x * v1.x + v1.y * v1.y + v1.z * v1.z + v1.w * v1.w;
        #pragma unroll
        for (int o = 16; o; o >>= 1) {
            s0 += __shfl_xor_sync(0xffffffffu, s0, o);
            s1 += __shfl_xor_sync(0xffffffffu, s1, o);
        }
        float i0 = 1.0f / fmaxf(sqrtf(s0), 1e-8f);
        float i1 = 1.0f / fmaxf(sqrtf(s1), 1e-8f);
        size_t b0 = (size_t)row0 * DD + lane * 4;
        *(__half2*)(g_h + b0)          = __floats2half2_rn(v0.x * i0, v0.y * i0);
        *(__half2*)(g_h + b0 + 2)      = __floats2half2_rn(v0.z * i0, v0.w * i0);
        *(__half2*)(g_h + b0 + DD)     = __floats2half2_rn(v1.x * i1, v1.y * i1);
        *(__half2*)(g_h + b0 + DD + 2) = __floats2half2_rn(v1.z * i1, v1.w * i1);
    } else {
        __shared__ int ht[NCLS], htb[NCLS * NB];
        int tid = threadIdx.x;
        if (tid < NCLS)      ht[tid]  = 0;
        if (tid < NCLS * NB) htb[tid] = 0;
        __syncthreads();
        for (int i = tid; i < NN; i += blockDim.x) {
            int t = targets[i], b = batch0[i];
            atomicAdd(&ht[t], 1);
            atomicAdd(&htb[t * NB + b], 1);
        }
        __syncthreads();
        if (tid < NCLS)      g_hist_t[tid]  = ht[tid];
        if (tid < NCLS * NB) g_hist_tb[tid] = htb[tid];
    }
}

// ---------------------------------------------------------------------------
// Templated epilogue (DIAG: self-exclusion; FAST: t==0.25 -> et = eb*eb).
// ---------------------------------------------------------------------------
template <bool DIAG, bool FAST>
__device__ __forceinline__ void epilogue(
    const float (&acc)[4][4][4],
    const uint32_t (&kIa)[2], const uint32_t* kj8,
    float inv_t, float* red1, float* red2,
    int wm, int wn, int g, int q)
{
    float all2[8], st2[8], sb2[8], pb2[8];
    #pragma unroll
    for (int k = 0; k < 8; k++) { all2[k]=st2[k]=sb2[k]=pb2[k]=0.f; }

    #pragma unroll
    for (int mi = 0; mi < 4; mi++) {
        float a1[2] = {0.f, 0.f}, s1[2] = {0.f, 0.f};
        float b1[2] = {0.f, 0.f}, p1[2] = {0.f, 0.f};
        uint32_t kib[2];
        #pragma unroll
        for (int h = 0; h < 2; h++) {
            int pi = mi * 2 + h;
            kib[h] = (kIa[pi >> 2] >> ((pi & 3) * 8)) & 0xFFu;
        }

        #pragma unroll
        for (int ni = 0; ni < 4; ni++) {
            #pragma unroll
            for (int e = 0; e < 4; e++) {
                const int h  = e >> 1, l = e & 1;
                const int pj = ni * 2 + l;
                uint32_t x = kib[h] ^ kj8[pj];
                bool same_t = (x < 8u);
                bool eq     = (x == 0u);
                float s  = acc[mi][ni][e];
                float eb, et;
                if (FAST) { eb = __expf(s + s); et = eb * eb; }
                else      { eb = __expf(s + s); et = __expf(s * inv_t); }
                if (DIAG) {
                    bool self = ((wm * 64 + mi * 16 + h * 8 + g) ==
                                 (wn * 32 + ni * 8 + 2 * q + l));
                    et = self ? 0.f : et;
                    eb = self ? 0.f : eb;
                }
                float et_st = same_t ? et : 0.f;
                float eb_st = same_t ? eb : 0.f;
                float eb_eq = eq     ? eb : 0.f;
                a1[h] += et;    s1[h] += et_st;   b1[h] += eb_st;   p1[h] += eb_eq;
                all2[pj] += et; st2[pj] += et_st; sb2[pj] += eb_st; pb2[pj] += eb_eq;
            }
        }
        #pragma unroll
        for (int h = 0; h < 2; h++) {
            float pt = s1[h];
            float nt = a1[h] - s1[h];
            float pb = p1[h];
            float nb = b1[h] - p1[h];
            #pragma unroll
            for (int o = 1; o <= 2; o <<= 1) {
                pt += __shfl_xor_sync(0xffffffffu, pt, o);
                nt += __shfl_xor_sync(0xffffffffu, nt, o);
                pb += __shfl_xor_sync(0xffffffffu, pb, o);
                nb += __shfl_xor_sync(0xffffffffu, nb, o);
            }
            if (q == 0) {
                int row_loc = wm * 64 + mi * 16 + h * 8 + g;
                *(float4*)&red1[(wn * 128 + row_loc) * 4] = make_float4(pt, nt, pb, nb);
            }
        }
    }

    if (!DIAG) {
        #pragma unroll
        for (int k = 0; k < 8; k++) {
            float pt = st2[k];
            float nt = all2[k] - st2[k];
            float pb = pb2[k];
            float nb = sb2[k] - pb2[k];
            #pragma unroll
            for (int o = 4; o <= 16; o <<= 1) {
                pt += __shfl_xor_sync(0xffffffffu, pt, o);
                nt += __shfl_xor_sync(0xffffffffu, nt, o);
                pb += __shfl_xor_sync(0xffffffffu, pb, o);
                nb += __shfl_xor_sync(0xffffffffu, nb, o);
            }
            if (g == 0) {
                int row_loc = wn * 32 + (k >> 1) * 8 + 2 * q + (k & 1);
                *(float4*)&red2[(wm * 128 + row_loc) * 4] = make_float4(pt, nt, pb, nb);
            }
        }
    }
}

// ---------------------------------------------------------------------------
// Kernel 2: one CTA per tile pair (I,J), I<=J.
// ---------------------------------------------------------------------------
__device__ __forceinline__ void fill_tile(char* smem, int off,
                                          const __half* __restrict__ src,
                                          int rowbase, int tid) {
    #pragma unroll
    for (int it = 0; it < 8; it++) {
        int lin = it * 256 + tid;
        int n   = lin >> 4;
        int c16 = lin & 15;
        uint4 v = *(const uint4*)(src + (size_t)(rowbase + n) * DD + c16 * 8);
        *(uint4*)(smem + off + n * 256 + ((c16 ^ (n & 7)) << 4)) = v;
    }
}

__global__ void __launch_bounds__(256, 2)
k_main(const float* __restrict__ d_temp,
       const int*   __restrict__ targets,
       const int*   __restrict__ batch0) {
    extern __shared__ char smem[];
    const uint32_t sb = smem_u32(smem);
    const int tid = threadIdx.x;
    const int L   = tid & 31;
    const int w   = tid >> 5;
    const int wm  = w & 1;
    const int wn  = w >> 1;

    int p = blockIdx.x, I = 0;
    while (p >= ITILES - I) { p -= ITILES - I; I++; }
    const int J = I + p;
    const int Ibase = I * 128;
    const int Jbase = J * 128;
    const bool diag = (I == J);

    int*   sm_ki = (int*)(smem + OFF_KI);
    int*   sm_kj = (int*)(smem + OFF_KJ);
    float* red1  = (float*)(smem + OFF_RED1);
    float* red2  = (float*)(smem + OFF_RED2);

    const float t     = fminf(fmaxf(d_temp[0], 0.1f), 1.0f);
    const float inv_t = 1.0f / t;
    const bool  fast  = (inv_t == 4.0f);

    fill_tile(smem, OFF_A, g_h, Ibase, tid);
    fill_tile(smem, OFF_B, g_h, Jbase, tid);
    if (tid < 128) {
        sm_ki[tid] = targets[Ibase + tid] * 8 + batch0[Ibase + tid];
    } else {
        int r = tid - 128;
        sm_kj[r] = targets[Jbase + r] * 8 + batch0[Jbase + r];
    }
    __syncthreads();

    const int la15 = L & 15;
    const int l4   = L >> 4;
    const int lb7  = (L & 7) + ((L >> 4) << 3);
    const int lb1  = (L >> 3) & 1;

    float acc[4][4][4];
    #pragma unroll
    for (int mi = 0; mi < 4; mi++)
        #pragma unroll
        for (int ni = 0; ni < 4; ni++)
            #pragma unroll
            for (int e = 0; e < 4; e++) acc[mi][ni][e] = 0.f;

    #pragma unroll
    for (int ks = 0; ks < 8; ks++) {
        uint32_t a[4][4], b[2][4];
        #pragma unroll
        for (int mi = 0; mi < 4; mi++) {
            int rowA = wm * 64 + mi * 16 + la15;
            uint32_t ad = sb + OFF_A + rowA * 256 + (((ks * 2 + l4) ^ (rowA & 7)) << 4);
            LDSM_X4(a[mi][0], a[mi][1], a[mi][2], a[mi][3], ad);
        }
        #pragma unroll
        for (int np = 0; np < 2; np++) {
            int rowB = wn * 32 + np * 16 + lb7;
            uint32_t bd = sb + OFF_B + rowB * 256 + (((ks * 2 + lb1) ^ (rowB & 7)) << 4);
            LDSM_X4(b[np][0], b[np][1], b[np][2], b[np][3], bd);
        }
        #pragma unroll
        for (int mi = 0; mi < 4; mi++)
            #pragma unroll
            for (int ni = 0; ni < 4; ni++)
                MMA_F16(acc[mi][ni], a[mi],
                        b[ni >> 1][(ni & 1) * 2], b[ni >> 1][(ni & 1) * 2 + 1]);
    }

    const int g = L >> 2, q = L & 3;

    uint32_t kIa[2] = {0u, 0u};
    uint32_t kj8[8];
    #pragma unroll
    for (int pk = 0; pk < 8; pk++) {
        int row = wm * 64 + (pk >> 1) * 16 + (pk & 1) * 8 + g;
        kIa[pk >> 2] |= ((uint32_t)sm_ki[row]) << ((pk & 3) * 8);
        int col = wn * 32 + (pk >> 1) * 8 + 2 * q + (pk & 1);
        kj8[pk] = (uint32_t)sm_kj[col];
    }
    __syncthreads();

    if (diag) {
        if (fast) epilogue<true,  true >(acc, kIa, kj8, inv_t, red1, red2, wm, wn, g, q);
        else      epilogue<true,  false>(acc, kIa, kj8, inv_t, red1, red2, wm, wn, g, q);
    } else {
        if (fast) epilogue<false, true >(acc, kIa, kj8, inv_t, red1, red2, wm, wn, g, q);
        else      epilogue<false, false>(acc, kIa, kj8, inv_t, red1, red2, wm, wn, g, q);
    }
    __syncthreads();

    if (tid < 128) {
        float a = 0.f, b = 0.f, c = 0.f, d = 0.f;
        #pragma unroll
        for (int v = 0; v < 4; v++) {
            float4 r4 = *(const float4*)&red1[(v * 128 + tid) * 4];
            a += r4.x; b += r4.y; c += r4.z; d += r4.w;
        }
        *(float4*)(g_part + ((size_t)(Ibase + tid) * JSPLIT + J) * 4) = make_float4(a, b, c, d);
    } else if (!diag) {
        int r = tid - 128;
        float4 r0 = *(const float4*)&red2[(r) * 4];
        float4 r1 = *(const float4*)&red2[(128 + r) * 4];
        *(float4*)(g_part + ((size_t)(Jbase + r) * JSPLIT + I) * 4) =
            make_float4(r0.x + r1.x, r0.y + r1.y, r0.z + r1.z, r0.w + r1.w);
    }
}

// ---------------------------------------------------------------------------
// Kernel 3: tail, one warp per row (768 blocks x 256 thr; 8 rows/block).
// Component index of each lane's loads is invariant (lane&3), so xor-shuffles
// over {4,8,16} reduce each of the 4 components independently.
// ---------------------------------------------------------------------------
__global__ void k_tail(const int* __restrict__ targets,
                       const int* __restrict__ batch0) {
    __shared__ float sm_lt[8], sm_lb[8];
    __shared__ int   sm_t[8],  sm_b[8];

    const int tid  = threadIdx.x;
    const int warp = tid >> 5;                // local row 0..7
    const int lane = tid & 31;
    const int i    = blockIdx.x * 8 + warp;

    const float* rowp = g_part + (size_t)i * (JSPLIT * 4);   // 192 floats
    float v = 0.f;
    #pragma unroll
    for (int m = 0; m < 6; m++) v += rowp[lane + m * 32];    // coalesced
    #pragma unroll
    for (int o = 4; o <= 16; o <<= 1) v += __shfl_xor_sync(0xffffffffu, v, o);

    float ptv = __shfl_sync(0xffffffffu, v, 0);
    float ntv = __shfl_sync(0xffffffffu, v, 1);
    float pbv = __shfl_sync(0xffffffffu, v, 2);
    float nbv = __shfl_sync(0xffffffffu, v, 3);

    if (lane == 0) {
        int tcl = targets[i], bcl = batch0[i];
        int cp  = g_hist_t[tcl];
        bool valid_t = (cp >= 2) && ((NN - cp) >= 1);
        int cpb = g_hist_tb[tcl * NB + bcl];
        int cnb = cp - cpb;
        bool valid_b = (cpb >= 2) && (cnb >= 1);
        sm_lt[warp] = valid_t ? logf((ptv + ntv) / ptv) : 0.0f;
        sm_lb[warp] = valid_b ? (1.0f / logf((pbv + nbv) / pbv)) : 0.0f;
        sm_t[warp]  = tcl;
        sm_b[warp]  = bcl;
    }
    __syncthreads();

    if (tid < NCLS + NB) {
        float s = 0.f;
        if (tid < NCLS) {
            #pragma unroll
            for (int k = 0; k < 8; k++)
                if (sm_t[k] == tid) s += sm_lt[k];
        } else {
            int bc = tid - NCLS;
            #pragma unroll
            for (int k = 0; k < 8; k++)
                if (sm_b[k] == bc) s += sm_lb[k];
        }
        g_blk[tid * TBLK + blockIdx.x] = s;     // class-major
    }
}

// ---------------------------------------------------------------------------
// Kernel 4: final scalar (1024 threads).  32 lanes per class, contiguous reads.
// ---------------------------------------------------------------------------
__global__ void k_fin(const float* __restrict__ w_t,
                      const float* __restrict__ w_b,
                      float* __restrict__ out) {
    __shared__ float tot_sm[32];
    int tid  = threadIdx.x;
    int c    = tid >> 5;                  // 0..31
    int lane = tid & 31;

    float s = 0.f;
    if (c < NCLS + NB) {
        const float4* base = (const float4*)(g_blk + c * TBLK + lane * 24);
        #pragma unroll
        for (int m = 0; m < 6; m++) {
            float4 v = base[m];
            s += v.x + v.y + v.z + v.w;
        }
    }
    #pragma unroll
    for (int o = 16; o; o >>= 1) s += __shfl_xor_sync(0xffffffffu, s, o);
    if (lane == 0) tot_sm[c] = s;
    __syncthreads();

    if (tid < 32) {
        float tot = tot_sm[tid];
        float contrib = 0.f;
        if (tid < NCLS) {
            int cp = g_hist_t[tid];
            bool valid = (cp >= 2) && ((NN - cp) >= 1);
            float cnt = valid ? (float)cp : 0.f;
            float mean = tot / fmaxf(cnt, 1.0f);
            if (cnt > 0.f) contrib = 0.9f * mean * w_t[tid];
        } else if (tid < NCLS + NB) {
            int bc = tid - NCLS;
            float cnt = 0.f;
            for (int tc = 0; tc < NCLS; tc++) {
                int cpb = g_hist_tb[tc * NB + bc];
                int cnb = g_hist_t[tc] - cpb;
                if ((cpb >= 2) && (cnb >= 1)) cnt += (float)cpb;
            }
            float mean = tot / fmaxf(cnt, 1.0f);
            if (cnt > 0.f) contrib = 0.1f * mean * w_b[bc];
        }
        #pragma unroll
        for (int o = 16; o; o >>= 1) contrib += __shfl_xor_sync(0xffffffffu, contrib, o);
        if (tid == 0) out[0] = contrib;
    }
}

// ---------------------------------------------------------------------------
extern "C" void kernel_launch(void* const* d_in, const int* in_sizes, int n_in,
                              void* d_out, int out_size) {
    const float* x       = (const float*)d_in[0];
    const float* temp    = (const float*)d_in[1];
    const float* w_t     = (const float*)d_in[2];
    const float* w_b     = (const float*)d_in[3];
    const int*   targets = (const int*)d_in[4];
    const int*   batch0  = (const int*)d_in[5];
    float*       out     = (float*)d_out;

    k_prep<<<NORMB + 1, 256>>>(x, targets, batch0);

    cudaFuncSetAttribute(k_main, cudaFuncAttributeMaxDynamicSharedMemorySize, SMEM_TOTAL);
    k_main<<<NPAIRS, 256, SMEM_TOTAL>>>(temp, targets, batch0);

    k_tail<<<TBLK, 256>>>(targets, batch0);
    k_fin<<<1, 1024>>>(w_t, w_b, out);
}